// round 3
// baseline (speedup 1.0000x reference)
#include <cuda_runtime.h>
#include <cstdint>

#define SP 7
#define MM 8
#define DD 1008
#define H0 256
#define H1 192
#define H2 160
#define NMAX 50400
#define GMAX (NMAX / SP)
#define BATCH (SP * MM)
#define HB 112
#define EB 1024

// -------- scratch (device globals; no allocation allowed) --------
__device__ int   d_idx[NMAX];
__device__ int   d_hist[HB * SP];
__device__ int   d_off[HB * SP];
__device__ float d_h0[(size_t)BATCH * GMAX * H0];   // 413 MB
__device__ float d_h1[(size_t)BATCH * GMAX * H1];   // 310 MB
__device__ float d_h2[(size_t)BATCH * GMAX * H2];   // 258 MB
__device__ float d_part[EB];

__device__ __forceinline__ float celu_f(float x) {
    return x > 0.f ? x : 0.1f * expm1f(x * 10.0f);
}

// -------- stable species bucketing (deterministic) --------
__global__ void k_hist(const int* __restrict__ sp, int n, int chunk) {
    __shared__ int h[SP];
    if (threadIdx.x < SP) h[threadIdx.x] = 0;
    __syncthreads();
    int b = blockIdx.x;
    int beg = b * chunk;
    int end = min(n, beg + chunk);
    for (int i = beg + threadIdx.x; i < end; i += blockDim.x)
        atomicAdd(&h[sp[i]], 1);
    __syncthreads();
    if (threadIdx.x < SP) d_hist[b * SP + threadIdx.x] = h[threadIdx.x];
}

__global__ void k_scan(int G) {
    int s = threadIdx.x;
    if (s >= SP) return;
    int acc = s * G;
    for (int b = 0; b < HB; b++) {
        d_off[b * SP + s] = acc;
        acc += d_hist[b * SP + s];
    }
}

__global__ void k_place(const int* __restrict__ sp, int n, int chunk) {
    if (threadIdx.x != 0) return;
    int b = blockIdx.x;
    int beg = b * chunk;
    int end = min(n, beg + chunk);
    int loc[SP];
#pragma unroll
    for (int s = 0; s < SP; s++) loc[s] = d_off[b * SP + s];
    for (int i = beg; i < end; i++) {
        int s = sp[i];
        d_idx[loc[s]++] = i;
    }
}

// -------- batched tiled SGEMM with fused gather / CELU / bias --------
// C[bm][g][j] = sum_k act(A[bm][g][k]) * W[bm][k][j] + bias[bm][j]
// LAYER 0: A = aev gathered via d_idx (no act), C = d_h0
// LAYER 1: A = celu(d_h0), C = d_h1
// LAYER 2: A = celu(d_h1), C = d_h2
template <int KD, int NO, int LAYER>
__global__ void __launch_bounds__(128)
k_gemm(const float* __restrict__ Ain, const float* __restrict__ W,
       const float* __restrict__ bias, int G) {
    const int t  = threadIdx.x;
    const int bm = blockIdx.z;
    const int gt = blockIdx.x * 64;
    const int nt = blockIdx.y * 64;

    const float* __restrict__ A;
    float* __restrict__ C;
    if (LAYER == 0)      { A = Ain;  C = d_h0; }
    else if (LAYER == 1) { A = d_h0; C = d_h1; }
    else                 { A = d_h1; C = d_h2; }

    const float* __restrict__ Wp = W    + (size_t)bm * KD * NO;
    const float* __restrict__ bp = bias + (size_t)bm * NO;
    float* __restrict__ Cp       = C    + (size_t)bm * G * NO;

    __shared__ float As[16][68];  // padded, stored transposed [k][row]
    __shared__ float Bs[16][64];

    // A-tile load mapping: thread -> (row 0..63, k-offset 0 or 8)
    const int arow  = t >> 1;
    const int akoff = (t & 1) * 8;
    const int ga    = gt + arow;
    const float* aptr = nullptr;
    if (ga < G) {
        if (LAYER == 0) {
            const int s = bm / MM;
            aptr = A + (size_t)d_idx[s * G + ga] * KD;
        } else {
            aptr = A + ((size_t)bm * G + ga) * KD;
        }
    }

    // B-tile load mapping: thread -> (k-row 0..15, col-offset multiple of 8)
    const int bk    = t >> 3;
    const int bcoff = (t & 7) * 8;
    const int cg    = nt + bcoff;
    const bool bvalid = (cg < NO);   // NO % 8 == 0 -> whole float4s guarded

    const int ty = t >> 4;   // 0..7  -> rows ty*8 .. ty*8+7
    const int tx = t & 15;   // 0..15 -> cols tx*4 .. tx*4+3

    float acc[8][4];
#pragma unroll
    for (int i = 0; i < 8; i++)
#pragma unroll
        for (int j = 0; j < 4; j++) acc[i][j] = 0.f;

    for (int k0 = 0; k0 < KD; k0 += 16) {
        float4 a0 = make_float4(0.f, 0.f, 0.f, 0.f);
        float4 a1 = make_float4(0.f, 0.f, 0.f, 0.f);
        if (aptr) {
            a0 = *(const float4*)(aptr + k0 + akoff);
            a1 = *(const float4*)(aptr + k0 + akoff + 4);
            if (LAYER != 0) {
                a0.x = celu_f(a0.x); a0.y = celu_f(a0.y);
                a0.z = celu_f(a0.z); a0.w = celu_f(a0.w);
                a1.x = celu_f(a1.x); a1.y = celu_f(a1.y);
                a1.z = celu_f(a1.z); a1.w = celu_f(a1.w);
            }
        }
        float4 b0 = make_float4(0.f, 0.f, 0.f, 0.f);
        float4 b1 = make_float4(0.f, 0.f, 0.f, 0.f);
        if (bvalid) {
            const float* wr = Wp + (size_t)(k0 + bk) * NO + cg;
            b0 = *(const float4*)(wr);
            b1 = *(const float4*)(wr + 4);
        }
        __syncthreads();  // previous iteration's compute done
        As[akoff + 0][arow] = a0.x;
        As[akoff + 1][arow] = a0.y;
        As[akoff + 2][arow] = a0.z;
        As[akoff + 3][arow] = a0.w;
        As[akoff + 4][arow] = a1.x;
        As[akoff + 5][arow] = a1.y;
        As[akoff + 6][arow] = a1.z;
        As[akoff + 7][arow] = a1.w;
        *(float4*)&Bs[bk][bcoff]     = b0;
        *(float4*)&Bs[bk][bcoff + 4] = b1;
        __syncthreads();

#pragma unroll
        for (int kk = 0; kk < 16; kk++) {
            float av[8];
#pragma unroll
            for (int i = 0; i < 8; i++) av[i] = As[kk][ty * 8 + i];
            const float4 bv = *(const float4*)&Bs[kk][tx * 4];
#pragma unroll
            for (int i = 0; i < 8; i++) {
                acc[i][0] = fmaf(av[i], bv.x, acc[i][0]);
                acc[i][1] = fmaf(av[i], bv.y, acc[i][1]);
                acc[i][2] = fmaf(av[i], bv.z, acc[i][2]);
                acc[i][3] = fmaf(av[i], bv.w, acc[i][3]);
            }
        }
    }

    const int c0 = nt + tx * 4;
    if (c0 < NO) {
        const float4 bb = *(const float4*)(bp + c0);
#pragma unroll
        for (int i = 0; i < 8; i++) {
            const int gi = gt + ty * 8 + i;
            if (gi < G) {
                float4 v;
                v.x = acc[i][0] + bb.x;
                v.y = acc[i][1] + bb.y;
                v.z = acc[i][2] + bb.z;
                v.w = acc[i][3] + bb.w;
                *(float4*)(Cp + (size_t)gi * NO + c0) = v;
            }
        }
    }
}

// -------- last layer (160 -> 1) + deterministic reduction --------
__global__ void k_energy(const float* __restrict__ W3,
                         const float* __restrict__ b3, int G) {
    const int lane = threadIdx.x & 31;
    const int wid  = threadIdx.x >> 5;
    const int nw   = blockDim.x >> 5;
    const int gw     = blockIdx.x * nw + wid;
    const int stride = gridDim.x * nw;
    const int R      = BATCH * G;

    float sum = 0.f;
    for (int r = gw; r < R; r += stride) {
        const int bm = r / G;
        const int g  = r - bm * G;
        const float* __restrict__ row = d_h2 + ((size_t)bm * G + g) * H2;
        const float* __restrict__ w   = W3 + (size_t)bm * H2;
        float d = 0.f;
#pragma unroll
        for (int i = lane; i < H2; i += 32)
            d = fmaf(celu_f(row[i]), w[i], d);
#pragma unroll
        for (int off = 16; off > 0; off >>= 1)
            d += __shfl_xor_sync(0xFFFFFFFFu, d, off);
        if (lane == 0) sum += d + b3[bm];
    }
    __shared__ float ws[32];
    if (lane == 0) ws[wid] = sum;
    __syncthreads();
    if (threadIdx.x == 0) {
        float p = 0.f;
        for (int i = 0; i < nw; i++) p += ws[i];   // fixed order -> deterministic
        d_part[blockIdx.x] = p;
    }
}

__global__ void k_final(float* __restrict__ out) {
    __shared__ float sh[EB];
    const int tid = threadIdx.x;
    sh[tid] = d_part[tid];
    __syncthreads();
    for (int s = EB / 2; s > 0; s >>= 1) {
        if (tid < s) sh[tid] += sh[tid + s];
        __syncthreads();
    }
    if (tid == 0) out[0] = sh[0] * (1.0f / (float)MM);
}

// -------- harness entry --------
extern "C" void kernel_launch(void* const* d_in, const int* in_sizes, int n_in,
                              void* d_out, int out_size) {
    const int*   species = (const int*)d_in[0];
    const float* aev     = (const float*)d_in[1];
    const float* W0 = (const float*)d_in[2];
    const float* b0 = (const float*)d_in[3];
    const float* W1 = (const float*)d_in[4];
    const float* b1 = (const float*)d_in[5];
    const float* W2 = (const float*)d_in[6];
    const float* b2 = (const float*)d_in[7];
    const float* W3 = (const float*)d_in[8];
    const float* b3 = (const float*)d_in[9];
    float* out = (float*)d_out;

    const int N = in_sizes[0];
    const int G = N / SP;
    const int chunk = (N + HB - 1) / HB;

    k_hist<<<HB, 256>>>(species, N, chunk);
    k_scan<<<1, 32>>>(G);
    k_place<<<HB, 32>>>(species, N, chunk);

    dim3 g1((G + 63) / 64, (H0 + 63) / 64, BATCH);
    k_gemm<DD, H0, 0><<<g1, 128>>>(aev, W0, b0, G);

    dim3 g2((G + 63) / 64, (H1 + 63) / 64, BATCH);
    k_gemm<H0, H1, 1><<<g2, 128>>>(nullptr, W1, b1, G);

    dim3 g3((G + 63) / 64, (H2 + 63) / 64, BATCH);
    k_gemm<H1, H2, 2><<<g3, 128>>>(nullptr, W2, b2, G);

    k_energy<<<EB, 256>>>(W3, b3, G);
    k_final<<<1, EB>>>(out);
}

// round 5
// speedup vs baseline: 1.5508x; 1.5508x over previous
#include <cuda_runtime.h>
#include <cuda_bf16.h>
#include <cstdint>

#define SP 7
#define MM 8
#define DD 1008
#define H0 256
#define H1 192
#define H2 160
#define NMAX 50400
#define GMAX (NMAX / SP)
#define BATCH (SP * MM)
#define HB 112
#define EB 1024

// ---------------- scratch (device globals; no allocation allowed) ------------
__device__ int d_idx[NMAX];
__device__ int d_hist[HB * SP];
__device__ int d_off[HB * SP];

// [hi | lo] split buffers, K-contiguous rows of width 2*K
__device__ __align__(16) __nv_bfloat16 d_a0[(size_t)NMAX * 2 * DD];
__device__ __align__(16) __nv_bfloat16 d_w0[(size_t)BATCH * H0 * 2 * DD];
__device__ __align__(16) __nv_bfloat16 d_w1[(size_t)BATCH * H1 * 2 * H0];
__device__ __align__(16) __nv_bfloat16 d_w2[(size_t)BATCH * H2 * 2 * H1];
__device__ __align__(16) __nv_bfloat16 d_a1[(size_t)BATCH * GMAX * 2 * H0];
__device__ __align__(16) __nv_bfloat16 d_a2[(size_t)BATCH * GMAX * 2 * H1];
__device__ float d_h2[(size_t)BATCH * GMAX * H2];
__device__ float d_part[EB];

__device__ __forceinline__ float celu_f(float x) {
    return x > 0.f ? x : 0.1f * expm1f(x * 10.0f);
}

// ---------------- PTX helpers (all baseline sm_80+ features) ------------------
__device__ __forceinline__ uint32_t smem_u32(const void* p) {
    uint32_t a;
    asm("{ .reg .u64 t; cvta.to.shared.u64 t, %1; cvt.u32.u64 %0, t; }"
        : "=r"(a) : "l"(p));
    return a;
}
__device__ __forceinline__ void cp16(uint32_t s, const void* g) {
    asm volatile("cp.async.cg.shared.global [%0], [%1], 16;" :: "r"(s), "l"(g));
}
__device__ __forceinline__ void cp_commit() {
    asm volatile("cp.async.commit_group;" ::: "memory");
}
template <int N>
__device__ __forceinline__ void cp_wait() {
    asm volatile("cp.async.wait_group %0;" :: "n"(N) : "memory");
}
__device__ __forceinline__ void ldsm_x4(uint32_t& r0, uint32_t& r1,
                                        uint32_t& r2, uint32_t& r3, uint32_t a) {
    asm volatile("ldmatrix.sync.aligned.m8n8.x4.shared.b16 {%0,%1,%2,%3}, [%4];"
                 : "=r"(r0), "=r"(r1), "=r"(r2), "=r"(r3) : "r"(a));
}
__device__ __forceinline__ void ldsm_x2(uint32_t& r0, uint32_t& r1, uint32_t a) {
    asm volatile("ldmatrix.sync.aligned.m8n8.x2.shared.b16 {%0,%1}, [%2];"
                 : "=r"(r0), "=r"(r1) : "r"(a));
}
__device__ __forceinline__ void mma16816(float* c, const uint32_t* a, const uint32_t* b) {
    asm volatile(
        "mma.sync.aligned.m16n8k16.row.col.f32.bf16.bf16.f32 "
        "{%0,%1,%2,%3}, {%4,%5,%6,%7}, {%8,%9}, {%0,%1,%2,%3};"
        : "+f"(c[0]), "+f"(c[1]), "+f"(c[2]), "+f"(c[3])
        : "r"(a[0]), "r"(a[1]), "r"(a[2]), "r"(a[3]), "r"(b[0]), "r"(b[1]));
}

// ---------------- stable species bucketing (deterministic) -------------------
__global__ void k_hist(const int* __restrict__ sp, int n, int chunk) {
    __shared__ int h[SP];
    if (threadIdx.x < SP) h[threadIdx.x] = 0;
    __syncthreads();
    int b = blockIdx.x;
    int beg = b * chunk, end = min(n, beg + chunk);
    for (int i = beg + threadIdx.x; i < end; i += blockDim.x)
        atomicAdd(&h[sp[i]], 1);
    __syncthreads();
    if (threadIdx.x < SP) d_hist[b * SP + threadIdx.x] = h[threadIdx.x];
}
__global__ void k_scan(int G) {
    int s = threadIdx.x;
    if (s >= SP) return;
    int acc = s * G;
    for (int b = 0; b < HB; b++) { d_off[b * SP + s] = acc; acc += d_hist[b * SP + s]; }
}
__global__ void k_place(const int* __restrict__ sp, int n, int chunk) {
    if (threadIdx.x != 0) return;
    int b = blockIdx.x;
    int beg = b * chunk, end = min(n, beg + chunk);
    int loc[SP];
#pragma unroll
    for (int s = 0; s < SP; s++) loc[s] = d_off[b * SP + s];
    for (int i = beg; i < end; i++) d_idx[loc[sp[i]]++] = i;
}

// ---------------- prep: gather+split AEV, transpose+split weights ------------
__global__ void k_prep_aev(const float* __restrict__ aev) {
    int r = blockIdx.x;
    const float* src = aev + (size_t)d_idx[r] * DD;
    size_t dst = (size_t)r * (2 * DD);
    for (int k = threadIdx.x; k < DD; k += blockDim.x) {
        float v = src[k];
        __nv_bfloat16 h = __float2bfloat16(v);
        d_a0[dst + k] = h;
        d_a0[dst + DD + k] = __float2bfloat16(v - __bfloat162float(h));
    }
}

__global__ void k_wsplit(const float* __restrict__ W, int K, int N, int layer) {
    __shared__ float tile[32][33];
    int bm = blockIdx.z;
    int n0 = blockIdx.x * 32, k0 = blockIdx.y * 32;
    const float* Wp = W + (size_t)bm * K * N;
    for (int r = threadIdx.y; r < 32; r += 8) {
        int k = k0 + r, n = n0 + threadIdx.x;
        tile[r][threadIdx.x] = (k < K && n < N) ? Wp[(size_t)k * N + n] : 0.f;
    }
    __syncthreads();
    __nv_bfloat16* O;
    if (layer == 0)      O = d_w0;
    else if (layer == 1) O = d_w1;
    else                 O = d_w2;
    for (int r = threadIdx.y; r < 32; r += 8) {
        int n = n0 + r, k = k0 + threadIdx.x;
        if (n < N && k < K) {
            float v = tile[threadIdx.x][r];
            __nv_bfloat16 h = __float2bfloat16(v);
            size_t o = ((size_t)bm * N + n) * (size_t)(2 * K) + k;
            O[o] = h;
            O[o + K] = __float2bfloat16(v - __bfloat162float(h));
        }
    }
}

// ---------------- bf16 HMMA batched GEMM (3-term split via K sections) -------
// D[128 x NOUT] = A[128 x K'] * W^T, K' = 3K realized as sections
//   s0: (Ah,Bh)  s1: (Al,Bh)  s2: (Ah,Bl)    [drops Al*Bl ~ 2^-18]
// Epilogue: +bias, CELU; LAYER<2 -> hi/lo split store, LAYER==2 -> fp32.
template <int K, int NOUT, int LAYER>
__global__ void __launch_bounds__(256, 1)
k_mma(const float* __restrict__ bias, int G) {
    constexpr int KPS = K / 16;
    constexpr int TOTAL = 3 * KPS;
    constexpr int NS = 4;

    __shared__ __align__(16) __nv_bfloat16 As[NS][128][24];  // 48B pitch (odd*16B)
    __shared__ __align__(16) __nv_bfloat16 Bs[NS][64][24];

    const int t = threadIdx.x;
    const int lane = t & 31;
    const int wid = t >> 5;
    const int wr = wid >> 1;   // 0..3 -> 32-row slab
    const int wc = wid & 1;    // 0..1 -> 32-col slab
    const int bm = blockIdx.z;
    const int gt = blockIdx.x * 128;
    const int ntb = blockIdx.y * 64;

    const __nv_bfloat16* Ag;
    const __nv_bfloat16* Wg;
    size_t aBase;
    if (LAYER == 0)      { Ag = d_a0; Wg = d_w0; aBase = (size_t)(bm / MM) * G; }
    else if (LAYER == 1) { Ag = d_a1; Wg = d_w1; aBase = (size_t)bm * G; }
    else                 { Ag = d_a2; Wg = d_w2; aBase = (size_t)bm * G; }

    // per-thread load sources (row clamped; garbage rows never stored)
    const int arow = t >> 1, ach = t & 1;
    const int growc = min(gt + arow, G - 1);
    const __nv_bfloat16* aSrc =
        Ag + ((size_t)(aBase + growc)) * (size_t)(2 * K) + ach * 8;
    const int bn = min(ntb + ((t & 127) >> 1), NOUT - 1);
    const __nv_bfloat16* bSrc =
        Wg + ((size_t)bm * NOUT + bn) * (size_t)(2 * K) + (t & 1) * 8;

    auto load_stage = [&](int st, int it) {
        int sec = it / KPS, w = it - sec * KPS;
        int ak = (sec == 1 ? K : 0) + w * 16;
        int bk = (sec == 2 ? K : 0) + w * 16;
        cp16(smem_u32(&As[st][arow][ach * 8]), aSrc + ak);
        if (t < 128) cp16(smem_u32(&Bs[st][t >> 1][(t & 1) * 8]), bSrc + bk);
        cp_commit();
    };

    float acc[2][4][4];
#pragma unroll
    for (int i = 0; i < 2; i++)
#pragma unroll
        for (int j = 0; j < 4; j++)
#pragma unroll
            for (int k = 0; k < 4; k++) acc[i][j][k] = 0.f;

    // ldmatrix lane address offsets (bytes), 48B row pitch
    const uint32_t aoff = (uint32_t)((wr * 32 + (lane & 15)) * 48 + (lane >> 4) * 16);
    const uint32_t boff = (uint32_t)((wc * 32 + (lane & 7)) * 48 + ((lane >> 3) & 1) * 16);

#pragma unroll 1
    for (int s = 0; s < NS - 1; s++) load_stage(s, s);

#pragma unroll 1
    for (int i = 0; i < TOTAL; i++) {
        cp_wait<NS - 2>();
        __syncthreads();
        if (i + NS - 1 < TOTAL) load_stage((i + NS - 1) & 3, i + NS - 1);
        else cp_commit();

        const int st = i & 3;
        const uint32_t ab = smem_u32(&As[st][0][0]);
        const uint32_t bb = smem_u32(&Bs[st][0][0]);
        uint32_t aF[2][4], bF[4][2];
        ldsm_x4(aF[0][0], aF[0][1], aF[0][2], aF[0][3], ab + aoff);
        ldsm_x4(aF[1][0], aF[1][1], aF[1][2], aF[1][3], ab + aoff + 16 * 48);
#pragma unroll
        for (int nt = 0; nt < 4; nt++)
            ldsm_x2(bF[nt][0], bF[nt][1], bb + boff + nt * 8 * 48);
#pragma unroll
        for (int mt = 0; mt < 2; mt++)
#pragma unroll
            for (int nt = 0; nt < 4; nt++)
                mma16816(acc[mt][nt], aF[mt], bF[nt]);
    }

    // -------- epilogue: bias + CELU (+ hi/lo resplit) --------
    const float* bp = bias + (size_t)bm * NOUT;
#pragma unroll
    for (int mt = 0; mt < 2; mt++) {
#pragma unroll
        for (int half = 0; half < 2; half++) {
            const int grow = gt + wr * 32 + mt * 16 + (lane >> 2) + half * 8;
            if (grow >= G) continue;
            size_t rb = ((size_t)bm * G + grow) *
                        (size_t)(LAYER < 2 ? 2 * NOUT : NOUT);
#pragma unroll
            for (int nt = 0; nt < 4; nt++) {
                const int col = ntb + wc * 32 + nt * 8 + (lane & 3) * 2;
                if (col >= NOUT) continue;
                float v0 = acc[mt][nt][half * 2 + 0] + __ldg(bp + col);
                float v1 = acc[mt][nt][half * 2 + 1] + __ldg(bp + col + 1);
                v0 = celu_f(v0);
                v1 = celu_f(v1);
                if (LAYER < 2) {
                    __nv_bfloat16 h0 = __float2bfloat16(v0);
                    __nv_bfloat16 h1 = __float2bfloat16(v1);
                    __nv_bfloat162 hh, ll;
                    hh.x = h0; hh.y = h1;
                    ll.x = __float2bfloat16(v0 - __bfloat162float(h0));
                    ll.y = __float2bfloat16(v1 - __bfloat162float(h1));
                    __nv_bfloat16* dst = (LAYER == 0) ? d_a1 : d_a2;
                    *(__nv_bfloat162*)(dst + rb + col) = hh;
                    *(__nv_bfloat162*)(dst + rb + NOUT + col) = ll;
                } else {
                    float2 vv; vv.x = v0; vv.y = v1;
                    *(float2*)(d_h2 + rb + col) = vv;
                }
            }
        }
    }
}

// ---------------- last layer (160 -> 1) + deterministic reduction ------------
__global__ void k_energy(const float* __restrict__ W3,
                         const float* __restrict__ b3, int G) {
    const int lane = threadIdx.x & 31;
    const int wid = threadIdx.x >> 5;
    const int nw = blockDim.x >> 5;
    const int gw = blockIdx.x * nw + wid;
    const int stride = gridDim.x * nw;
    const int R = BATCH * G;

    float sum = 0.f;
    for (int r = gw; r < R; r += stride) {
        const int bm = r / G;
        const int g = r - bm * G;
        const float* __restrict__ row = d_h2 + ((size_t)bm * G + g) * H2;
        const float* __restrict__ w = W3 + (size_t)bm * H2;
        float d = 0.f;
#pragma unroll
        for (int i = lane; i < H2; i += 32)
            d = fmaf(row[i], w[i], d);   // h2 already CELU'd in GEMM epilogue
#pragma unroll
        for (int off = 16; off > 0; off >>= 1)
            d += __shfl_xor_sync(0xFFFFFFFFu, d, off);
        if (lane == 0) sum += d + b3[bm];
    }
    __shared__ float ws[32];
    if (lane == 0) ws[wid] = sum;
    __syncthreads();
    if (threadIdx.x == 0) {
        float p = 0.f;
        for (int i = 0; i < nw; i++) p += ws[i];
        d_part[blockIdx.x] = p;
    }
}

__global__ void k_final(float* __restrict__ out) {
    __shared__ float sh[EB];
    const int tid = threadIdx.x;
    sh[tid] = d_part[tid];
    __syncthreads();
    for (int s = EB / 2; s > 0; s >>= 1) {
        if (tid < s) sh[tid] += sh[tid + s];
        __syncthreads();
    }
    if (tid == 0) out[0] = sh[0] * (1.0f / (float)MM);
}

// ---------------- harness entry ----------------------------------------------
extern "C" void kernel_launch(void* const* d_in, const int* in_sizes, int n_in,
                              void* d_out, int out_size) {
    const int* species = (const int*)d_in[0];
    const float* aev = (const float*)d_in[1];
    const float* W0 = (const float*)d_in[2];
    const float* b0 = (const float*)d_in[3];
    const float* W1 = (const float*)d_in[4];
    const float* b1 = (const float*)d_in[5];
    const float* W2 = (const float*)d_in[6];
    const float* b2 = (const float*)d_in[7];
    const float* W3 = (const float*)d_in[8];
    const float* b3 = (const float*)d_in[9];
    float* out = (float*)d_out;

    const int N = in_sizes[0];
    const int G = N / SP;
    const int chunk = (N + HB - 1) / HB;

    // bucketing
    k_hist<<<HB, 256>>>(species, N, chunk);
    k_scan<<<1, 32>>>(G);
    k_place<<<HB, 32>>>(species, N, chunk);

    // prep: gather+split AEV, transpose+split weights
    k_prep_aev<<<N, 256>>>(aev);
    {
        dim3 g0((H0 + 31) / 32, (DD + 31) / 32, BATCH);
        k_wsplit<<<g0, dim3(32, 8)>>>(W0, DD, H0, 0);
        dim3 g1((H1 + 31) / 32, (H0 + 31) / 32, BATCH);
        k_wsplit<<<g1, dim3(32, 8)>>>(W1, H0, H1, 1);
        dim3 g2((H2 + 31) / 32, (H1 + 31) / 32, BATCH);
        k_wsplit<<<g2, dim3(32, 8)>>>(W2, H1, H2, 2);
    }

    const int gtiles = (G + 127) / 128;
    k_mma<DD, H0, 0><<<dim3(gtiles, (H0 + 63) / 64, BATCH), 256>>>(b0, G);
    k_mma<H0, H1, 1><<<dim3(gtiles, (H1 + 63) / 64, BATCH), 256>>>(b1, G);
    k_mma<H1, H2, 2><<<dim3(gtiles, (H2 + 63) / 64, BATCH), 256>>>(b2, G);

    k_energy<<<EB, 256>>>(W3, b3, G);
    k_final<<<1, EB>>>(out);
}